// round 2
// baseline (speedup 1.0000x reference)
#include <cuda_runtime.h>

// RoIAlign, NCHW fp32, OUT 7x7, sampling_ratio 2, scale 0.25
// features: (2, 256, 200, 304), rois: (512, 5), out: (512, 256, 7, 7)
//
// Lane mapping per warp (covers one output bin-row `oy` of CH_PER_WARP channels):
//   lanes  0..13 : corner x0   for x-samples sx=0..13
//   lanes 16..29 : corner x0+1 for x-samples sx=0..13
//   lanes 14,15,30,31 idle (weights forced to 0)
// Every LDG touches exactly ONE feature row (row base is warp-uniform), so each
// load instruction spans <=2 cache lines. The two gy sample rows per bin-row
// need rows {t0, t0+1, t1, t1+1}; warp-uniform branches dedupe overlapping rows
// down to 2 or 3 loads in the common cases.

namespace {
constexpr int OUT_H = 7;
constexpr int OUT_W = 7;
constexpr int C     = 256;
constexpr int H     = 200;
constexpr int W     = 304;
constexpr int R     = 512;
constexpr float SCALE = 0.25f;

constexpr int WARPS_PER_BLOCK = 8;
constexpr int GROUPS          = 4;                           // gridDim.y
constexpr int WARPS_PER_ROI   = WARPS_PER_BLOCK * GROUPS;    // 32
constexpr int CH_PER_WARP     = C / WARPS_PER_ROI;           // 8
constexpr int PLANE           = H * W;                       // 60800
}

__global__ __launch_bounds__(WARPS_PER_BLOCK * 32)
void roi_align_kernel(const float* __restrict__ feat,
                      const float* __restrict__ rois,
                      float* __restrict__ out)
{
    const int r      = blockIdx.x;
    const int warpId = threadIdx.x >> 5;
    const int lane   = threadIdx.x & 31;
    const int wroi   = blockIdx.y * WARPS_PER_BLOCK + warpId;   // 0..31
    const int c0     = wroi * CH_PER_WARP;

    // Per-roi constants (warp-uniform)
    const float bf  = rois[r * 5 + 0];
    const float rx1 = rois[r * 5 + 1] * SCALE - 0.5f;
    const float ry1 = rois[r * 5 + 2] * SCALE - 0.5f;
    const float rx2 = rois[r * 5 + 3] * SCALE - 0.5f;
    const float ry2 = rois[r * 5 + 4] * SCALE - 0.5f;
    const int   b   = (int)bf;

    const float bin_w = (rx2 - rx1) * (1.0f / OUT_W);
    const float bin_h = (ry2 - ry1) * (1.0f / OUT_H);

    // ---- x-geometry: oy-invariant, hoisted ----
    const int  sx       = lane & 15;        // 0..15 (14,15 idle)
    const bool active   = sx < 14;
    const bool cornerHi = lane >= 16;

    float wx  = 0.0f;   // per-lane x-weight (includes x-validity)
    int   col = 0;      // per-lane column index
    if (active) {
        float x = rx1 + (float)(sx >> 1) * bin_w
                      + ((float)(sx & 1) + 0.5f) * bin_w * 0.5f;
        bool  vx = (x > -1.0f) && (x < (float)W);
        float xc = fminf(fmaxf(x, 0.0f), (float)(W - 1));
        int   x0 = (int)xc;                  // xc >= 0 -> trunc == floor
        float lx = xc - (float)x0;
        float hx = 1.0f - lx;
        col = cornerHi ? min(x0 + 1, W - 1) : x0;
        wx  = (cornerHi ? lx : hx) * (vx ? 1.0f : 0.0f);
    }

    const float* planes = feat + ((size_t)b * C + c0) * PLANE;
    float*       outp   = out + ((size_t)r * C + c0) * (OUT_H * OUT_W);

    for (int oy = 0; oy < OUT_H; ++oy) {
        // ---- y-geometry (warp-uniform scalars) ----
        float yg0 = ry1 + (float)oy * bin_h + 0.25f * bin_h;
        float yg1 = yg0 + 0.5f * bin_h;

        bool  vy0 = (yg0 > -1.0f) && (yg0 < (float)H);
        float yc0 = fminf(fmaxf(yg0, 0.0f), (float)(H - 1));
        int   t0  = (int)yc0;
        float ly0 = yc0 - (float)t0;
        float hy0 = 1.0f - ly0;
        int   b0  = min(t0 + 1, H - 1);

        bool  vy1 = (yg1 > -1.0f) && (yg1 < (float)H);
        float yc1 = fminf(fmaxf(yg1, 0.0f), (float)(H - 1));
        int   t1  = (int)yc1;
        float ly1 = yc1 - (float)t1;
        float hy1 = 1.0f - ly1;
        int   b1  = min(t1 + 1, H - 1);

        // Row weights: fold y-validity and the 0.25 sample mean.
        float c0w = 0.25f * hy0 * (vy0 ? 1.0f : 0.0f);  // row t0 (gy0 top)
        float c1w = 0.25f * ly0 * (vy0 ? 1.0f : 0.0f);  // row b0 (gy0 bot)
        float c2w = 0.25f * hy1 * (vy1 ? 1.0f : 0.0f);  // row t1 (gy1 top)
        float c3w = 0.25f * ly1 * (vy1 ? 1.0f : 0.0f);  // row b1 (gy1 bot)

        const int rT0 = t0 * W + col;
        const int rB0 = b0 * W + col;
        const int rT1 = t1 * W + col;
        const int rB1 = b1 * W + col;

        float acc[CH_PER_WARP];
        if (t1 == t0) {
            // gy rows coincide: 2 loads
            const float wA = c0w + c2w;
            const float wB = c1w + c3w;
            #pragma unroll
            for (int cc = 0; cc < CH_PER_WARP; ++cc) {
                const float* p = planes + cc * PLANE;
                float vA = __ldg(p + rT0);
                float vB = __ldg(p + rB0);
                acc[cc] = wA * vA + wB * vB;
            }
        } else if (t1 == b0) {
            // overlapping middle row: 3 loads
            const float wM = c1w + c2w;
            #pragma unroll
            for (int cc = 0; cc < CH_PER_WARP; ++cc) {
                const float* p = planes + cc * PLANE;
                float v0 = __ldg(p + rT0);
                float v1 = __ldg(p + rB0);
                float v2 = __ldg(p + rB1);
                acc[cc] = c0w * v0 + wM * v1 + c3w * v2;
            }
        } else {
            // disjoint: 4 loads
            #pragma unroll
            for (int cc = 0; cc < CH_PER_WARP; ++cc) {
                const float* p = planes + cc * PLANE;
                float v0 = __ldg(p + rT0);
                float v1 = __ldg(p + rB0);
                float v2 = __ldg(p + rT1);
                float v3 = __ldg(p + rB1);
                acc[cc] = c0w * v0 + c1w * v1 + c2w * v2 + c3w * v3;
            }
        }

        #pragma unroll
        for (int cc = 0; cc < CH_PER_WARP; ++cc) {
            float a = wx * acc[cc];
            a += __shfl_down_sync(0xffffffffu, a, 16);  // sum corners x0 + x0+1
            a += __shfl_down_sync(0xffffffffu, a, 1);   // sum x-sample pairs
            if (lane < 14 && (lane & 1) == 0) {
                outp[(size_t)cc * (OUT_H * OUT_W) + oy * OUT_W + (lane >> 1)] = a;
            }
        }
    }
}

extern "C" void kernel_launch(void* const* d_in, const int* in_sizes, int n_in,
                              void* d_out, int out_size)
{
    const float* feat = (const float*)d_in[0];
    const float* rois = (const float*)d_in[1];
    float*       out  = (float*)d_out;

    dim3 grid(R, GROUPS);
    dim3 block(WARPS_PER_BLOCK * 32);
    roi_align_kernel<<<grid, block>>>(feat, rois, out);
}

// round 3
// speedup vs baseline: 1.2006x; 1.2006x over previous
#include <cuda_runtime.h>

// RoIAlign, NCHW fp32, OUT 7x7, sampling_ratio 2, scale 0.25
// features: (2, 256, 200, 304), rois: (512, 5), out: (512, 256, 7, 7)
//
// Warp covers one roi x 4 channels, processed as 2 channel-pairs.
// Lane mapping (per pair p):
//   lanes  0..13 : channel 2p+0, x-sample sx = lane
//   lanes 16..29 : channel 2p+1, x-sample sx = lane-16
//   lanes 14,15,30,31 idle (validity weight 0)
// Each lane computes the FULL bilinear sum for its x-sample across both gy
// sample rows (8 loads: 4 rows x 2 corner columns) -- the x-grid does not
// depend on gy, so x0/lx are shared. Only one shfl (sx-pair sum) and one
// predicated STG per channel-pair remain, cutting warp LSU issues from
// 7 to 5 per channel-bin-row versus the previous best kernel.

namespace {
constexpr int OUT_H = 7;
constexpr int OUT_W = 7;
constexpr int C     = 256;
constexpr int H     = 200;
constexpr int W     = 304;
constexpr int R     = 512;
constexpr float SCALE = 0.25f;

constexpr int WARPS_PER_BLOCK = 8;
constexpr int GROUPS          = 8;                          // gridDim.y
constexpr int WARPS_PER_ROI   = WARPS_PER_BLOCK * GROUPS;   // 64
constexpr int CH_PER_WARP     = C / WARPS_PER_ROI;          // 4
constexpr int PAIRS           = CH_PER_WARP / 2;            // 2
constexpr int PLANE           = H * W;                      // 60800
}

__global__ __launch_bounds__(WARPS_PER_BLOCK * 32)
void roi_align_kernel(const float* __restrict__ feat,
                      const float* __restrict__ rois,
                      float* __restrict__ out)
{
    const int r      = blockIdx.x;
    const int warpId = threadIdx.x >> 5;
    const int lane   = threadIdx.x & 31;
    const int wroi   = blockIdx.y * WARPS_PER_BLOCK + warpId;  // 0..63
    const int c0     = wroi * CH_PER_WARP;

    // Per-roi constants (warp-uniform)
    const float bf  = rois[r * 5 + 0];
    const float rx1 = rois[r * 5 + 1] * SCALE - 0.5f;
    const float ry1 = rois[r * 5 + 2] * SCALE - 0.5f;
    const float rx2 = rois[r * 5 + 3] * SCALE - 0.5f;
    const float ry2 = rois[r * 5 + 4] * SCALE - 0.5f;
    const int   b   = (int)bf;

    const float bin_w = (rx2 - rx1) * (1.0f / OUT_W);
    const float bin_h = (ry2 - ry1) * (1.0f / OUT_H);

    // ---- x-geometry: oy-invariant, per-lane ----
    const int  sx     = lane & 15;      // 0..15 (14,15 idle)
    const bool active = sx < 14;
    const int  half   = lane >> 4;      // 0: even channel, 1: odd channel

    float hx = 0.0f, lx = 0.0f, vxf = 0.0f;
    int   colA = 0, colB = 0;
    if (active) {
        float x = rx1 + (float)(sx >> 1) * bin_w
                      + ((float)(sx & 1) + 0.5f) * bin_w * 0.5f;
        bool  vx = (x > -1.0f) && (x < (float)W);
        float xc = fminf(fmaxf(x, 0.0f), (float)(W - 1));
        int   x0 = (int)xc;                 // xc >= 0 -> trunc == floor
        lx   = xc - (float)x0;
        hx   = 1.0f - lx;
        colA = x0;
        colB = min(x0 + 1, W - 1);
        vxf  = vx ? 1.0f : 0.0f;
    }

    // Per-lane channel base: pair p uses channel c0 + 2p + half
    const float* base = feat + ((size_t)b * C + (c0 + half)) * PLANE;
    float*       outp = out + ((size_t)r * C + c0) * (OUT_H * OUT_W);

    for (int oy = 0; oy < OUT_H; ++oy) {
        // ---- y-geometry (warp-uniform) ----
        float yg0 = ry1 + (float)oy * bin_h + 0.25f * bin_h;
        float yg1 = yg0 + 0.5f * bin_h;

        float vy0 = ((yg0 > -1.0f) && (yg0 < (float)H)) ? 1.0f : 0.0f;
        float yc0 = fminf(fmaxf(yg0, 0.0f), (float)(H - 1));
        int   t0  = (int)yc0;
        float ly0 = yc0 - (float)t0;
        int   b0  = min(t0 + 1, H - 1);

        float vy1 = ((yg1 > -1.0f) && (yg1 < (float)H)) ? 1.0f : 0.0f;
        float yc1 = fminf(fmaxf(yg1, 0.0f), (float)(H - 1));
        int   t1  = (int)yc1;
        float ly1 = yc1 - (float)t1;
        int   b1  = min(t1 + 1, H - 1);

        // Row weights: fold 0.25 sample-mean and y-validity.
        float w0 = 0.25f * (1.0f - ly0) * vy0;   // row t0
        float w1 = 0.25f * ly0 * vy0;            // row b0
        float w2 = 0.25f * (1.0f - ly1) * vy1;   // row t1
        float w3 = 0.25f * ly1 * vy1;            // row b1

        const int rT0 = t0 * W, rB0 = b0 * W, rT1 = t1 * W, rB1 = b1 * W;

        #pragma unroll
        for (int p = 0; p < PAIRS; ++p) {
            const float* pl = base + (size_t)(2 * p) * PLANE;
            float vT0A = __ldg(pl + rT0 + colA);
            float vT0B = __ldg(pl + rT0 + colB);
            float vB0A = __ldg(pl + rB0 + colA);
            float vB0B = __ldg(pl + rB0 + colB);
            float vT1A = __ldg(pl + rT1 + colA);
            float vT1B = __ldg(pl + rT1 + colB);
            float vB1A = __ldg(pl + rB1 + colA);
            float vB1B = __ldg(pl + rB1 + colB);

            float aT0 = hx * vT0A + lx * vT0B;
            float aB0 = hx * vB0A + lx * vB0B;
            float aT1 = hx * vT1A + lx * vT1B;
            float aB1 = hx * vB1A + lx * vB1B;

            float v = vxf * (w0 * aT0 + w1 * aB0 + w2 * aT1 + w3 * aB1);

            // sum the two x-samples of each output bin
            v += __shfl_down_sync(0xffffffffu, v, 1);

            if (active && (sx & 1) == 0) {
                int ch = 2 * p + half;
                outp[(size_t)ch * (OUT_H * OUT_W) + oy * OUT_W + (sx >> 1)] = v;
            }
        }
    }
}

extern "C" void kernel_launch(void* const* d_in, const int* in_sizes, int n_in,
                              void* d_out, int out_size)
{
    const float* feat = (const float*)d_in[0];
    const float* rois = (const float*)d_in[1];
    float*       out  = (float*)d_out;

    dim3 grid(R, GROUPS);
    dim3 block(WARPS_PER_BLOCK * 32);
    roi_align_kernel<<<grid, block>>>(feat, rois, out);
}

// round 4
// speedup vs baseline: 1.4575x; 1.2140x over previous
#include <cuda_runtime.h>

// RoIAlign, NCHW fp32, OUT 7x7, sampling_ratio 2, scale 0.25
// features: (2, 256, 200, 304), rois: (512, 5), out: (512, 256, 7, 7)
//
// Warp = (roi, 4 channels). Lane = (corner, x-sample):
//   lanes  0..13 : corner x0   for x-samples sx=0..13
//   lanes 16..29 : corner x0+1 for x-samples sx=0..13
//   lanes 14,15,30,31 idle (x-weight 0)
// Every LDG reads ONE feature row (row base warp-uniform, per-lane column) ->
// 1-2 cache lines per instruction. The 14 y-samples are walked in order with a
// two-row register cache (rows rA=t_j, rB=t_j+1, values for 4 channels). Since
// consecutive y-samples are <= 1.8 px apart, t_{j+1} is usually rA (0 loads) or
// rB (4 loads, one per channel); only jumps load 8. This removes the cross-oy
// row redundancy that kept L1 wavefront work flat in rounds 1-3.

namespace {
constexpr int OUT_H = 7;
constexpr int OUT_W = 7;
constexpr int C     = 256;
constexpr int H     = 200;
constexpr int W     = 304;
constexpr int R     = 512;
constexpr float SCALE = 0.25f;

constexpr int WARPS_PER_BLOCK = 8;
constexpr int GROUPS          = 8;                          // gridDim.y
constexpr int WARPS_PER_ROI   = WARPS_PER_BLOCK * GROUPS;   // 64
constexpr int CH_PER_WARP     = C / WARPS_PER_ROI;          // 4
constexpr int PLANE           = H * W;                      // 60800
}

__global__ __launch_bounds__(WARPS_PER_BLOCK * 32)
void roi_align_kernel(const float* __restrict__ feat,
                      const float* __restrict__ rois,
                      float* __restrict__ out)
{
    const int r      = blockIdx.x;
    const int warpId = threadIdx.x >> 5;
    const int lane   = threadIdx.x & 31;
    const int wroi   = blockIdx.y * WARPS_PER_BLOCK + warpId;  // 0..63
    const int c0     = wroi * CH_PER_WARP;

    // Per-roi constants (warp-uniform)
    const float bf  = rois[r * 5 + 0];
    const float rx1 = rois[r * 5 + 1] * SCALE - 0.5f;
    const float ry1 = rois[r * 5 + 2] * SCALE - 0.5f;
    const float rx2 = rois[r * 5 + 3] * SCALE - 0.5f;
    const float ry2 = rois[r * 5 + 4] * SCALE - 0.5f;
    const int   b   = (int)bf;

    const float bin_w = (rx2 - rx1) * (1.0f / OUT_W);
    const float bin_h = (ry2 - ry1) * (1.0f / OUT_H);

    // ---- x-geometry: oy-invariant, per-lane ----
    const int  sx     = lane & 15;      // 0..15 (14,15 idle)
    const bool active = sx < 14;
    const bool hiCor  = lane >= 16;

    float wx  = 0.0f;   // x-weight incl. x-validity
    int   col = 0;
    if (active) {
        float x = rx1 + (float)(sx >> 1) * bin_w
                      + ((float)(sx & 1) + 0.5f) * bin_w * 0.5f;
        bool  vx = (x > -1.0f) && (x < (float)W);
        float xc = fminf(fmaxf(x, 0.0f), (float)(W - 1));
        int   x0 = (int)xc;                 // xc >= 0 -> trunc == floor
        float lx = xc - (float)x0;
        col = hiCor ? min(x0 + 1, W - 1) : x0;
        wx  = (hiCor ? lx : (1.0f - lx)) * (vx ? 1.0f : 0.0f);
    }

    // Per-lane plane base: channel c0+cc, plus per-lane column offset folded in.
    const float* pbase = feat + ((size_t)b * C + c0) * PLANE + col;
    float*       outp  = out + ((size_t)r * C + c0) * (OUT_H * OUT_W);

    // Two-row register cache across the y-sample walk
    int   rA = -1000000, rB = -1000000;   // cached row indices (rB == min(rA+1, H-1))
    float vA[CH_PER_WARP], vB[CH_PER_WARP];
    #pragma unroll
    for (int cc = 0; cc < CH_PER_WARP; ++cc) { vA[cc] = 0.f; vB[cc] = 0.f; }

    for (int oy = 0; oy < OUT_H; ++oy) {
        float bacc[CH_PER_WARP];

        #pragma unroll
        for (int g = 0; g < 2; ++g) {
            // y-sample geometry (warp-uniform)
            float yg = ry1 + (float)oy * bin_h + (0.25f + 0.5f * (float)g) * bin_h;
            float vy = ((yg > -1.0f) && (yg < (float)H)) ? 1.0f : 0.0f;
            float yc = fminf(fmaxf(yg, 0.0f), (float)(H - 1));
            int   t  = (int)yc;
            float ly = yc - (float)t;
            int   bb = min(t + 1, H - 1);
            float wT = 0.25f * (1.0f - ly) * vy;
            float wB = 0.25f * ly * vy;

            float nT[CH_PER_WARP], nB[CH_PER_WARP];
            if (t == rA) {
                // fully cached (bb == rB since rB = min(rA+1, H-1))
                #pragma unroll
                for (int cc = 0; cc < CH_PER_WARP; ++cc) { nT[cc] = vA[cc]; nB[cc] = vB[cc]; }
            } else if (t == rB) {
                // shift: old bottom becomes new top, load new bottom row
                const int ro = bb * W;
                #pragma unroll
                for (int cc = 0; cc < CH_PER_WARP; ++cc) nT[cc] = vB[cc];
                #pragma unroll
                for (int cc = 0; cc < CH_PER_WARP; ++cc)
                    nB[cc] = __ldg(pbase + (size_t)cc * PLANE + ro);
            } else {
                // jump: load both rows
                const int roT = t * W, roB = bb * W;
                #pragma unroll
                for (int cc = 0; cc < CH_PER_WARP; ++cc)
                    nT[cc] = __ldg(pbase + (size_t)cc * PLANE + roT);
                #pragma unroll
                for (int cc = 0; cc < CH_PER_WARP; ++cc)
                    nB[cc] = __ldg(pbase + (size_t)cc * PLANE + roB);
            }
            rA = t; rB = bb;
            #pragma unroll
            for (int cc = 0; cc < CH_PER_WARP; ++cc) { vA[cc] = nT[cc]; vB[cc] = nB[cc]; }

            #pragma unroll
            for (int cc = 0; cc < CH_PER_WARP; ++cc) {
                float s = wT * nT[cc] + wB * nB[cc];
                bacc[cc] = (g == 0) ? s : (bacc[cc] + s);
            }
        }

        #pragma unroll
        for (int cc = 0; cc < CH_PER_WARP; ++cc) {
            float v = wx * bacc[cc];
            v += __shfl_down_sync(0xffffffffu, v, 16);  // sum the two corners
            v += __shfl_down_sync(0xffffffffu, v, 1);   // sum the x-sample pair
            if (lane < 14 && (lane & 1) == 0) {
                outp[(size_t)cc * (OUT_H * OUT_W) + oy * OUT_W + (sx >> 1)] = v;
            }
        }
    }
}

extern "C" void kernel_launch(void* const* d_in, const int* in_sizes, int n_in,
                              void* d_out, int out_size)
{
    const float* feat = (const float*)d_in[0];
    const float* rois = (const float*)d_in[1];
    float*       out  = (float*)d_out;

    dim3 grid(R, GROUPS);
    dim3 block(WARPS_PER_BLOCK * 32);
    roi_align_kernel<<<grid, block>>>(feat, rois, out);
}